// round 7
// baseline (speedup 1.0000x reference)
#include <cuda_runtime.h>
#include <cuda_bf16.h>

#define N_NODES_MAX 50000
#define HF 64

// Scratch tables: A[n] = h[n] @ W1[0:64,:] + b1, B[n] = h[n] @ W1[64:128,:]
__device__ float gA[N_NODES_MAX * HF];
__device__ float gB[N_NODES_MAX * HF];

// ---------------------------------------------------------------------------
// Kernel 1: per-node precompute (64 nodes x 128 cols tile, 256 thr, 4x8/thread)
// Plain FFMA; a-operands loaded 4 k-steps at a time via LDS.128 to raise the
// FMA share of issued instructions (24 -> 12 LDS per 4 k-steps).
// ---------------------------------------------------------------------------
__global__ __launch_bounds__(256) void node_precompute(
    const float* __restrict__ h,
    const float* __restrict__ W1,
    const float* __restrict__ b1,
    int n_nodes)
{
    __shared__ __align__(16) float sh[64 * 64];    // sh[m][k]
    __shared__ __align__(16) float sW[64 * 128];   // sW[k][jj]

    const int t = threadIdx.x;
    const int node0 = blockIdx.x * 64;

    for (int i = t; i < 64 * 128; i += 256) {
        int k  = i >> 7;
        int jj = i & 127;
        sW[i] = W1[(k + (jj & 64)) * 64 + (jj & 63)];
    }
    for (int i = t; i < 64 * 64; i += 256) {
        int m = i >> 6;
        int k = i & 63;
        int n = node0 + m;
        sh[i] = (n < n_nodes) ? h[n * 64 + k] : 0.f;
    }
    __syncthreads();

    const int tx = t & 15;   // jj0 = tx*8
    const int ty = t >> 4;   // m0  = ty*4

    float acc[4][8];
#pragma unroll
    for (int m = 0; m < 4; m++)
#pragma unroll
        for (int j = 0; j < 8; j++) acc[m][j] = 0.f;

#pragma unroll
    for (int k0 = 0; k0 < 64; k0 += 4) {
        float4 av[4];
#pragma unroll
        for (int m = 0; m < 4; m++)
            av[m] = *reinterpret_cast<const float4*>(&sh[(ty * 4 + m) * 64 + k0]);

#pragma unroll
        for (int kk = 0; kk < 4; kk++) {
            const int k = k0 + kk;
            const float4 w0 = *reinterpret_cast<const float4*>(&sW[k * 128 + tx * 8]);
            const float4 w1 = *reinterpret_cast<const float4*>(&sW[k * 128 + tx * 8 + 4]);
#pragma unroll
            for (int m = 0; m < 4; m++) {
                const float a = (kk == 0) ? av[m].x : (kk == 1) ? av[m].y
                              : (kk == 2) ? av[m].z : av[m].w;
                acc[m][0] = fmaf(a, w0.x, acc[m][0]);
                acc[m][1] = fmaf(a, w0.y, acc[m][1]);
                acc[m][2] = fmaf(a, w0.z, acc[m][2]);
                acc[m][3] = fmaf(a, w0.w, acc[m][3]);
                acc[m][4] = fmaf(a, w1.x, acc[m][4]);
                acc[m][5] = fmaf(a, w1.y, acc[m][5]);
                acc[m][6] = fmaf(a, w1.z, acc[m][6]);
                acc[m][7] = fmaf(a, w1.w, acc[m][7]);
            }
        }
    }

    const int jj0 = tx * 8;
    const bool isA = (jj0 < 64);
    float bb[8];
#pragma unroll
    for (int j = 0; j < 8; j++) bb[j] = isA ? __ldg(&b1[jj0 + j]) : 0.f;

#pragma unroll
    for (int m = 0; m < 4; m++) {
        int n = node0 + ty * 4 + m;
        if (n >= n_nodes) break;
        float* dst = isA ? (&gA[n * 64 + jj0]) : (&gB[n * 64 + (jj0 - 64)]);
        float4 o0 = make_float4(acc[m][0] + bb[0], acc[m][1] + bb[1],
                                acc[m][2] + bb[2], acc[m][3] + bb[3]);
        float4 o1 = make_float4(acc[m][4] + bb[4], acc[m][5] + bb[5],
                                acc[m][6] + bb[6], acc[m][7] + bb[7]);
        *reinterpret_cast<float4*>(dst)     = o0;
        *reinterpret_cast<float4*>(dst + 4) = o1;
    }
}

// ---------------------------------------------------------------------------
// Kernel 2: per-edge scoring (R4/R6 shape: 8 lanes/group, 2 edges/group).
// New: paired float2 stores in the epilogue — gl==0 already holds both edges'
// scores, and (e0, e0+1) are contiguous, so scores and labels each go out as
// one STG.64. Store wavefronts per warp: 16 -> 8, zero added shuffles.
// ---------------------------------------------------------------------------
__global__ __launch_bounds__(256) void edge_score(
    const int* __restrict__ src,
    const int* __restrict__ dst,
    const float* __restrict__ W2,
    const float* __restrict__ b2,
    float* __restrict__ out,
    int n_edges)
{
    const int tid = blockIdx.x * blockDim.x + threadIdx.x;
    const int gl  = threadIdx.x & 7;
    const int g   = tid >> 3;          // group id, handles edges 2g, 2g+1
    const int e0  = g * 2;
    if (e0 >= n_edges) return;
    const bool has1 = (e0 + 1) < n_edges;

    int s0, d0, s1, d1;
    if (has1) {
        const int2 ss = __ldg(reinterpret_cast<const int2*>(src) + g);
        const int2 dd = __ldg(reinterpret_cast<const int2*>(dst) + g);
        s0 = ss.x; s1 = ss.y; d0 = dd.x; d1 = dd.y;
    } else {
        s0 = __ldg(&src[e0]); d0 = __ldg(&dst[e0]); s1 = s0; d1 = d0;
    }

    const float4 w0 = __ldg(reinterpret_cast<const float4*>(W2) + gl);
    const float4 w1 = __ldg(reinterpret_cast<const float4*>(W2) + gl + 8);

    const float4* pa0 = reinterpret_cast<const float4*>(gA + (size_t)s0 * HF) + gl;
    const float4* pb0 = reinterpret_cast<const float4*>(gB + (size_t)d0 * HF) + gl;
    const float4* pa1 = reinterpret_cast<const float4*>(gA + (size_t)s1 * HF) + gl;
    const float4* pb1 = reinterpret_cast<const float4*>(gB + (size_t)d1 * HF) + gl;

    const float4 A0 = __ldg(pa0);
    const float4 A1 = __ldg(pa0 + 8);
    const float4 B0 = __ldg(pb0);
    const float4 B1 = __ldg(pb0 + 8);
    const float4 C0 = __ldg(pa1);
    const float4 C1 = __ldg(pa1 + 8);
    const float4 D0 = __ldg(pb1);
    const float4 D1 = __ldg(pb1 + 8);

    float p;
    p =       fmaxf(A0.x + B0.x, 0.f) * w0.x;
    p = fmaf( fmaxf(A0.y + B0.y, 0.f), w0.y, p);
    p = fmaf( fmaxf(A0.z + B0.z, 0.f), w0.z, p);
    p = fmaf( fmaxf(A0.w + B0.w, 0.f), w0.w, p);
    p = fmaf( fmaxf(A1.x + B1.x, 0.f), w1.x, p);
    p = fmaf( fmaxf(A1.y + B1.y, 0.f), w1.y, p);
    p = fmaf( fmaxf(A1.z + B1.z, 0.f), w1.z, p);
    p = fmaf( fmaxf(A1.w + B1.w, 0.f), w1.w, p);

    float q;
    q =       fmaxf(C0.x + D0.x, 0.f) * w0.x;
    q = fmaf( fmaxf(C0.y + D0.y, 0.f), w0.y, q);
    q = fmaf( fmaxf(C0.z + D0.z, 0.f), w0.z, q);
    q = fmaf( fmaxf(C0.w + D0.w, 0.f), w0.w, q);
    q = fmaf( fmaxf(C1.x + D1.x, 0.f), w1.x, q);
    q = fmaf( fmaxf(C1.y + D1.y, 0.f), w1.y, q);
    q = fmaf( fmaxf(C1.z + D1.z, 0.f), w1.z, q);
    q = fmaf( fmaxf(C1.w + D1.w, 0.f), w1.w, q);

    // width-8 reductions (interleaved)
    p += __shfl_xor_sync(0xFFFFFFFFu, p, 4);
    q += __shfl_xor_sync(0xFFFFFFFFu, q, 4);
    p += __shfl_xor_sync(0xFFFFFFFFu, p, 2);
    q += __shfl_xor_sync(0xFFFFFFFFu, q, 2);
    p += __shfl_xor_sync(0xFFFFFFFFu, p, 1);
    q += __shfl_xor_sync(0xFFFFFFFFu, q, 1);

    if (gl == 0) {
        const float bias = __ldg(&b2[0]);
        const float sc0 = p + bias;
        // label = round(sigmoid(score)); exact expf/rintf required
        // (a single label flip exceeds the 1e-3 rel-err budget)
        const float lb0 = rintf(1.f / (1.f + expf(-sc0)));
        if (has1) {
            const float sc1 = q + bias;
            const float lb1 = rintf(1.f / (1.f + expf(-sc1)));
            *reinterpret_cast<float2*>(out + e0)           = make_float2(sc0, sc1);
            *reinterpret_cast<float2*>(out + n_edges + e0) = make_float2(lb0, lb1);
        } else {
            out[e0]           = sc0;
            out[n_edges + e0] = lb0;
        }
    }
}

// ---------------------------------------------------------------------------
// Launch: inputs in order h, src, dst, W1, b1, W2, b2
// ---------------------------------------------------------------------------
extern "C" void kernel_launch(void* const* d_in, const int* in_sizes, int n_in,
                              void* d_out, int out_size)
{
    const float* h   = (const float*)d_in[0];
    const int*   src = (const int*)d_in[1];
    const int*   dst = (const int*)d_in[2];
    const float* W1  = (const float*)d_in[3];
    const float* b1  = (const float*)d_in[4];
    const float* W2  = (const float*)d_in[5];
    const float* b2  = (const float*)d_in[6];
    float* out = (float*)d_out;

    const int n_nodes = in_sizes[0] / HF;
    const int n_edges = in_sizes[1];

    const int blocks1 = (n_nodes + 63) / 64;
    node_precompute<<<blocks1, 256>>>(h, W1, b1, n_nodes);

    const long long groups = (n_edges + 1) / 2;          // 2 edges per 8-lane group
    const long long total_threads = groups * 8;
    const int blocks2 = (int)((total_threads + 255) / 256);
    edge_score<<<blocks2, 256>>>(src, dst, W2, b2, out, n_edges);
}

// round 10
// speedup vs baseline: 1.0008x; 1.0008x over previous
#include <cuda_runtime.h>
#include <cuda_bf16.h>

#define N_NODES_MAX 50000
#define HF 64

// Scratch tables: A[n] = h[n] @ W1[0:64,:] + b1, B[n] = h[n] @ W1[64:128,:]
__device__ float gA[N_NODES_MAX * HF];
__device__ float gB[N_NODES_MAX * HF];

// ---------------------------------------------------------------------------
// Kernel 1: per-node precompute (64 nodes x 128 cols tile, 256 thr, 4x8/thread)
// Proven R3/R6 version: plain FFMA, scalar a-loads from shared.
// ---------------------------------------------------------------------------
__global__ __launch_bounds__(256) void node_precompute(
    const float* __restrict__ h,
    const float* __restrict__ W1,
    const float* __restrict__ b1,
    int n_nodes)
{
    __shared__ float sh[64 * 64];    // sh[m][k]
    __shared__ float sW[64 * 128];   // sW[k][jj]

    const int t = threadIdx.x;
    const int node0 = blockIdx.x * 64;

    for (int i = t; i < 64 * 128; i += 256) {
        int k  = i >> 7;
        int jj = i & 127;
        sW[i] = W1[(k + (jj & 64)) * 64 + (jj & 63)];
    }
    for (int i = t; i < 64 * 64; i += 256) {
        int m = i >> 6;
        int k = i & 63;
        int n = node0 + m;
        sh[i] = (n < n_nodes) ? h[n * 64 + k] : 0.f;
    }
    __syncthreads();

    const int tx = t & 15;   // jj0 = tx*8
    const int ty = t >> 4;   // m0  = ty*4

    float acc[4][8];
#pragma unroll
    for (int m = 0; m < 4; m++)
#pragma unroll
        for (int j = 0; j < 8; j++) acc[m][j] = 0.f;

#pragma unroll 8
    for (int k = 0; k < 64; k++) {
        float a[4];
#pragma unroll
        for (int m = 0; m < 4; m++) a[m] = sh[(ty * 4 + m) * 64 + k];
        const float4 w0 = *reinterpret_cast<const float4*>(&sW[k * 128 + tx * 8]);
        const float4 w1 = *reinterpret_cast<const float4*>(&sW[k * 128 + tx * 8 + 4]);
#pragma unroll
        for (int m = 0; m < 4; m++) {
            acc[m][0] = fmaf(a[m], w0.x, acc[m][0]);
            acc[m][1] = fmaf(a[m], w0.y, acc[m][1]);
            acc[m][2] = fmaf(a[m], w0.z, acc[m][2]);
            acc[m][3] = fmaf(a[m], w0.w, acc[m][3]);
            acc[m][4] = fmaf(a[m], w1.x, acc[m][4]);
            acc[m][5] = fmaf(a[m], w1.y, acc[m][5]);
            acc[m][6] = fmaf(a[m], w1.z, acc[m][6]);
            acc[m][7] = fmaf(a[m], w1.w, acc[m][7]);
        }
    }

    const int jj0 = tx * 8;
    const bool isA = (jj0 < 64);
    float bb[8];
#pragma unroll
    for (int j = 0; j < 8; j++) bb[j] = isA ? __ldg(&b1[jj0 + j]) : 0.f;

#pragma unroll
    for (int m = 0; m < 4; m++) {
        int n = node0 + ty * 4 + m;
        if (n >= n_nodes) break;
        float* dst = isA ? (&gA[n * 64 + jj0]) : (&gB[n * 64 + (jj0 - 64)]);
        float4 o0 = make_float4(acc[m][0] + bb[0], acc[m][1] + bb[1],
                                acc[m][2] + bb[2], acc[m][3] + bb[3]);
        float4 o1 = make_float4(acc[m][4] + bb[4], acc[m][5] + bb[5],
                                acc[m][6] + bb[6], acc[m][7] + bb[7]);
        *reinterpret_cast<float4*>(dst)     = o0;
        *reinterpret_cast<float4*>(dst + 4) = o1;
    }
}

// ---------------------------------------------------------------------------
// Kernel 2: per-edge scoring (8 lanes/group, 2 edges/group, 8 edges/warp).
// __launch_bounds__(256, 7): cap regs at 36 to lift residency 1536->1792
// threads/SM; everything else is the proven R6 structure.
// ---------------------------------------------------------------------------
__global__ __launch_bounds__(256, 7) void edge_score(
    const int* __restrict__ src,
    const int* __restrict__ dst,
    const float* __restrict__ W2,
    const float* __restrict__ b2,
    float* __restrict__ out,
    int n_edges)
{
    const int tid = blockIdx.x * blockDim.x + threadIdx.x;
    const int gl  = threadIdx.x & 7;
    const int g   = tid >> 3;          // group id, handles edges 2g, 2g+1
    const int e0  = g * 2;
    if (e0 >= n_edges) return;
    const bool has1 = (e0 + 1) < n_edges;

    int s0, d0, s1, d1;
    if (has1) {
        const int2 ss = __ldg(reinterpret_cast<const int2*>(src) + g);
        const int2 dd = __ldg(reinterpret_cast<const int2*>(dst) + g);
        s0 = ss.x; s1 = ss.y; d0 = dd.x; d1 = dd.y;
    } else {
        s0 = __ldg(&src[e0]); d0 = __ldg(&dst[e0]); s1 = s0; d1 = d0;
    }

    const float4 w0 = __ldg(reinterpret_cast<const float4*>(W2) + gl);
    const float4 w1 = __ldg(reinterpret_cast<const float4*>(W2) + gl + 8);

    const float4* pa0 = reinterpret_cast<const float4*>(gA + (size_t)s0 * HF) + gl;
    const float4* pb0 = reinterpret_cast<const float4*>(gB + (size_t)d0 * HF) + gl;
    const float4* pa1 = reinterpret_cast<const float4*>(gA + (size_t)s1 * HF) + gl;
    const float4* pb1 = reinterpret_cast<const float4*>(gB + (size_t)d1 * HF) + gl;

    const float4 A0 = __ldg(pa0);
    const float4 A1 = __ldg(pa0 + 8);
    const float4 B0 = __ldg(pb0);
    const float4 B1 = __ldg(pb0 + 8);
    const float4 C0 = __ldg(pa1);
    const float4 C1 = __ldg(pa1 + 8);
    const float4 D0 = __ldg(pb1);
    const float4 D1 = __ldg(pb1 + 8);

    float p;
    p =       fmaxf(A0.x + B0.x, 0.f) * w0.x;
    p = fmaf( fmaxf(A0.y + B0.y, 0.f), w0.y, p);
    p = fmaf( fmaxf(A0.z + B0.z, 0.f), w0.z, p);
    p = fmaf( fmaxf(A0.w + B0.w, 0.f), w0.w, p);
    p = fmaf( fmaxf(A1.x + B1.x, 0.f), w1.x, p);
    p = fmaf( fmaxf(A1.y + B1.y, 0.f), w1.y, p);
    p = fmaf( fmaxf(A1.z + B1.z, 0.f), w1.z, p);
    p = fmaf( fmaxf(A1.w + B1.w, 0.f), w1.w, p);

    float q;
    q =       fmaxf(C0.x + D0.x, 0.f) * w0.x;
    q = fmaf( fmaxf(C0.y + D0.y, 0.f), w0.y, q);
    q = fmaf( fmaxf(C0.z + D0.z, 0.f), w0.z, q);
    q = fmaf( fmaxf(C0.w + D0.w, 0.f), w0.w, q);
    q = fmaf( fmaxf(C1.x + D1.x, 0.f), w1.x, q);
    q = fmaf( fmaxf(C1.y + D1.y, 0.f), w1.y, q);
    q = fmaf( fmaxf(C1.z + D1.z, 0.f), w1.z, q);
    q = fmaf( fmaxf(C1.w + D1.w, 0.f), w1.w, q);

    // width-8 reductions (interleaved)
    p += __shfl_xor_sync(0xFFFFFFFFu, p, 4);
    q += __shfl_xor_sync(0xFFFFFFFFu, q, 4);
    p += __shfl_xor_sync(0xFFFFFFFFu, p, 2);
    q += __shfl_xor_sync(0xFFFFFFFFu, q, 2);
    p += __shfl_xor_sync(0xFFFFFFFFu, p, 1);
    q += __shfl_xor_sync(0xFFFFFFFFu, q, 1);

    if (gl == 0) {
        const float bias = __ldg(&b2[0]);
        const float sc0 = p + bias;
        // label = round(sigmoid(score)); exact expf/rintf required
        // (a single label flip exceeds the 1e-3 rel-err budget)
        const float lb0 = rintf(1.f / (1.f + expf(-sc0)));
        if (has1) {
            const float sc1 = q + bias;
            const float lb1 = rintf(1.f / (1.f + expf(-sc1)));
            *reinterpret_cast<float2*>(out + e0)           = make_float2(sc0, sc1);
            *reinterpret_cast<float2*>(out + n_edges + e0) = make_float2(lb0, lb1);
        } else {
            out[e0]           = sc0;
            out[n_edges + e0] = lb0;
        }
    }
}

// ---------------------------------------------------------------------------
// Launch: inputs in order h, src, dst, W1, b1, W2, b2
// ---------------------------------------------------------------------------
extern "C" void kernel_launch(void* const* d_in, const int* in_sizes, int n_in,
                              void* d_out, int out_size)
{
    const float* h   = (const float*)d_in[0];
    const int*   src = (const int*)d_in[1];
    const int*   dst = (const int*)d_in[2];
    const float* W1  = (const float*)d_in[3];
    const float* b1  = (const float*)d_in[4];
    const float* W2  = (const float*)d_in[5];
    const float* b2  = (const float*)d_in[6];
    float* out = (float*)d_out;

    const int n_nodes = in_sizes[0] / HF;
    const int n_edges = in_sizes[1];

    const int blocks1 = (n_nodes + 63) / 64;
    node_precompute<<<blocks1, 256>>>(h, W1, b1, n_nodes);

    const long long groups = (n_edges + 1) / 2;          // 2 edges per 8-lane group
    const long long total_threads = groups * 8;
    const int blocks2 = (int)((total_threads + 255) / 256);
    edge_score<<<blocks2, 256>>>(src, dst, W2, b2, out, n_edges);
}